// round 1
// baseline (speedup 1.0000x reference)
#include <cuda_runtime.h>
#include <math.h>

#define BB 64
#define PP 16320
#define CC 81
#define OO 50
#define FTHRESH 0.5f

// ---------------- scratch (device globals; no allocation allowed) ----------------
__device__ float d_bto[BB * PP];   // best_truth_overlap
__device__ int   d_bti[BB * PP];   // best_truth_idx
__device__ int   d_bp [BB * OO];   // best prior per truth
__device__ float d_cec[BB * PP];   // mined conf CE (pos zeroed)
__device__ float d_ceo[BB * PP];   // mined obj  CE (pos zeroed)
__device__ int   d_npos[BB];
__device__ float d_acc[3];         // loss_l, loss_c, loss_obj accumulators

// ---------------- init ----------------
__global__ void k_init() {
    int t = threadIdx.x;
    if (t < 3) d_acc[t] = 0.f;
    if (t >= 32 && t < 32 + BB) d_npos[t - 32] = 0;
}

// ---------------- per-prior match: max/argmax over truths ----------------
__global__ void k_match_p(const float* __restrict__ priors,
                          const float* __restrict__ targets) {
    int b = blockIdx.y;
    __shared__ float s_t[OO * 5];
    if (threadIdx.x < OO * 5) s_t[threadIdx.x] = targets[b * OO * 5 + threadIdx.x];
    __syncthreads();
    int p = blockIdx.x * blockDim.x + threadIdx.x;
    if (p >= PP) return;

    float4 pr = ((const float4*)priors)[p];
    float px1 = pr.x - pr.z * 0.5f, py1 = pr.y - pr.w * 0.5f;
    float px2 = pr.x + pr.z * 0.5f, py2 = pr.y + pr.w * 0.5f;
    float pa = (px2 - px1) * (py2 - py1);

    float best = -1.0f; int bi = 0;
    for (int o = 0; o < OO; o++) {
        float tx1 = s_t[o * 5 + 0], ty1 = s_t[o * 5 + 1];
        float tx2 = s_t[o * 5 + 2], ty2 = s_t[o * 5 + 3];
        float iw = fminf(tx2, px2) - fmaxf(tx1, px1);
        float ih = fminf(ty2, py2) - fmaxf(ty1, py1);
        iw = fmaxf(iw, 0.f); ih = fmaxf(ih, 0.f);
        float inter = iw * ih;
        float ta = (tx2 - tx1) * (ty2 - ty1);
        float ov = inter / (ta + pa - inter);
        if (ov > best) { best = ov; bi = o; }   // strict > == first-max (jnp.argmax)
    }
    d_bto[b * PP + p] = best;
    d_bti[b * PP + p] = bi;
}

// ---------------- per-truth match: argmax over priors (one block per (b,o)) ----------------
__global__ void k_match_o(const float* __restrict__ priors,
                          const float* __restrict__ targets) {
    int b = blockIdx.x / OO, o = blockIdx.x % OO;
    const float* t = targets + (b * OO + o) * 5;
    float tx1 = t[0], ty1 = t[1], tx2 = t[2], ty2 = t[3];
    float ta = (tx2 - tx1) * (ty2 - ty1);

    unsigned long long best = 0ull;
    for (int p = threadIdx.x; p < PP; p += blockDim.x) {
        float4 pr = ((const float4*)priors)[p];
        float px1 = pr.x - pr.z * 0.5f, py1 = pr.y - pr.w * 0.5f;
        float px2 = pr.x + pr.z * 0.5f, py2 = pr.y + pr.w * 0.5f;
        float pa = (px2 - px1) * (py2 - py1);
        float iw = fmaxf(fminf(tx2, px2) - fmaxf(tx1, px1), 0.f);
        float ih = fmaxf(fminf(ty2, py2) - fmaxf(ty1, py1), 0.f);
        float inter = iw * ih;
        float ov = inter / (ta + pa - inter);
        // IoU >= 0 so float bits are order-preserving; ~p breaks ties toward smaller p
        unsigned long long pk = ((unsigned long long)__float_as_uint(ov) << 32)
                              | (unsigned)(0xFFFFFFFFu - (unsigned)p);
        if (pk > best) best = pk;
    }
    __shared__ unsigned long long s[256];
    s[threadIdx.x] = best;
    __syncthreads();
    for (int st = 128; st; st >>= 1) {
        if (threadIdx.x < st) {
            unsigned long long oth = s[threadIdx.x + st];
            if (oth > s[threadIdx.x]) s[threadIdx.x] = oth;
        }
        __syncthreads();
    }
    if (threadIdx.x == 0)
        d_bp[b * OO + o] = (int)(0xFFFFFFFFu - (unsigned)(s[0] & 0xFFFFFFFFu));
}

// ---------------- force best-prior matches (sequential per batch: last write wins) ----------------
__global__ void k_force() {
    int b = threadIdx.x;
    if (b >= BB) return;
    for (int o = 0; o < OO; o++) {
        int p = d_bp[b * OO + o];
        d_bto[b * PP + p] = 2.0f;
        d_bti[b * PP + p] = o;
    }
}

// ---------------- main pass: warp per (b,p), CE + loc loss + scratch CE arrays ----------------
__global__ void __launch_bounds__(256) k_main(const float* __restrict__ loc,
                                              const float* __restrict__ conf,
                                              const float* __restrict__ obj,
                                              const float* __restrict__ priors,
                                              const float* __restrict__ targets) {
    int gw = (blockIdx.x * blockDim.x + threadIdx.x) >> 5;
    int lane = threadIdx.x & 31;
    if (gw >= BB * PP) return;
    int b = gw / PP;
    int p = gw - b * PP;

    const float* crow = conf + (size_t)gw * CC;
    float a0 = crow[lane];
    float a1 = crow[lane + 32];
    float a2 = (lane < 17) ? crow[lane + 64] : -1e30f;

    float m = fmaxf(fmaxf(a0, a1), a2);
    #pragma unroll
    for (int s = 16; s; s >>= 1) m = fmaxf(m, __shfl_xor_sync(0xFFFFFFFFu, m, s));
    float sum = expf(a0 - m) + expf(a1 - m) + ((lane < 17) ? expf(a2 - m) : 0.f);
    #pragma unroll
    for (int s = 16; s; s >>= 1) sum += __shfl_xor_sync(0xFFFFFFFFu, sum, s);

    if (lane == 0) {
        float L = m + logf(sum);                     // lse(conf)
        float ov = d_bto[gw];
        int   ti = d_bti[gw];
        const float* t = targets + (b * OO + ti) * 5;
        int conft = (ov < FTHRESH) ? 0 : ((int)t[4] + 1);
        bool pos = conft > 0;

        float o0 = obj[2 * (size_t)gw], o1 = obj[2 * (size_t)gw + 1];
        float mo = fmaxf(o0, o1);
        float lseo = mo + logf(expf(o0 - mo) + expf(o1 - mo));

        // lse over (C+1)-way combined logit == L + lseo  (algebraic identity)
        float cec = (conft == 0) ? (lseo - o0)
                                 : (L + lseo - o1 - crow[conft - 1]);
        float ceo = lseo - (pos ? o1 : o0);

        d_cec[gw] = pos ? 0.f : fmaxf(cec, 0.f);   // clamp fp-noise negatives (rank last anyway)
        d_ceo[gw] = pos ? 0.f : fmaxf(ceo, 0.f);

        if (pos) {
            atomicAdd(&d_npos[b], 1);
            atomicAdd(&d_acc[1], cec);
            atomicAdd(&d_acc[2], ceo);
            float4 pr = ((const float4*)priors)[p];
            float x1 = t[0], y1 = t[1], x2 = t[2], y2 = t[3];
            float lt0 = ((x1 + x2) * 0.5f - pr.x) / (0.1f * pr.z);
            float lt1 = ((y1 + y2) * 0.5f - pr.y) / (0.1f * pr.w);
            float lt2 = logf((x2 - x1) / pr.z) / 0.2f;
            float lt3 = logf((y2 - y1) / pr.w) / 0.2f;
            float4 ld = ((const float4*)loc)[gw];
            float sacc = 0.f, d;
            d = ld.x - lt0; sacc += (fabsf(d) < 1.f) ? 0.5f * d * d : fabsf(d) - 0.5f;
            d = ld.y - lt1; sacc += (fabsf(d) < 1.f) ? 0.5f * d * d : fabsf(d) - 0.5f;
            d = ld.z - lt2; sacc += (fabsf(d) < 1.f) ? 0.5f * d * d : fabsf(d) - 0.5f;
            d = ld.w - lt3; sacc += (fabsf(d) < 1.f) ? 0.5f * d * d : fabsf(d) - 0.5f;
            atomicAdd(&d_acc[0], sacc);
        }
    }
}

// ---------------- hard-negative mining: exact top-k sum via 4x8-bit radix select ----------------
__global__ void __launch_bounds__(256) k_topk() {
    int b = blockIdx.y, which = blockIdx.x;
    const float* arr = (which ? d_ceo : d_cec) + (size_t)b * PP;
    int k = 3 * d_npos[b];
    if (k > PP - 1) k = PP - 1;
    if (k <= 0) return;

    __shared__ unsigned hist[256];
    __shared__ unsigned s_prefix;
    __shared__ int s_krem;
    unsigned prefix = 0;
    int krem = k;

    for (int pass = 0; pass < 4; pass++) {
        hist[threadIdx.x] = 0;
        __syncthreads();
        int shift = 24 - 8 * pass;
        for (int p = threadIdx.x; p < PP; p += blockDim.x) {
            unsigned u = __float_as_uint(arr[p]);   // all values >= 0 -> uint order == float order
            if (pass == 0 || (u >> (shift + 8)) == prefix)
                atomicAdd(&hist[(u >> shift) & 0xFF], 1u);
        }
        __syncthreads();
        if (threadIdx.x == 0) {
            int cum = 0, bin = 255;
            for (; bin > 0; bin--) {
                int c = (int)hist[bin];
                if (cum + c >= krem) break;
                cum += c;
            }
            s_prefix = (prefix << 8) | (unsigned)bin;
            s_krem = krem - cum;
        }
        __syncthreads();
        prefix = s_prefix;
        krem = s_krem;
        __syncthreads();
    }
    unsigned vbits = prefix;
    float v = __uint_as_float(vbits);

    // sum of values strictly above the k-th value, plus remaining copies of v
    float sum = 0.f; int cnt = 0;
    for (int p = threadIdx.x; p < PP; p += blockDim.x) {
        float x = arr[p];
        if (__float_as_uint(x) > vbits) { sum += x; cnt++; }
    }
    __shared__ float ss[256];
    __shared__ int sc[256];
    ss[threadIdx.x] = sum; sc[threadIdx.x] = cnt;
    __syncthreads();
    for (int st = 128; st; st >>= 1) {
        if (threadIdx.x < st) {
            ss[threadIdx.x] += ss[threadIdx.x + st];
            sc[threadIdx.x] += sc[threadIdx.x + st];
        }
        __syncthreads();
    }
    if (threadIdx.x == 0)
        atomicAdd(&d_acc[1 + which], ss[0] + (float)(k - sc[0]) * v);
}

// ---------------- finalize ----------------
__global__ void k_final(float* __restrict__ out) {
    int n = 0;
    for (int b = 0; b < BB; b++) n += d_npos[b];
    float N = (float)n;
    out[0] = d_acc[0] / N;
    out[1] = d_acc[1] / N;
    out[2] = d_acc[2] / N;
}

// ---------------- launch ----------------
extern "C" void kernel_launch(void* const* d_in, const int* in_sizes, int n_in,
                              void* d_out, int out_size) {
    const float* loc     = (const float*)d_in[0];
    const float* conf    = (const float*)d_in[1];
    const float* obj     = (const float*)d_in[2];
    const float* priors  = (const float*)d_in[3];
    const float* targets = (const float*)d_in[4];
    float* out = (float*)d_out;

    k_init<<<1, 128>>>();

    dim3 g1((PP + 255) / 256, BB);
    k_match_p<<<g1, 256>>>(priors, targets);
    k_match_o<<<BB * OO, 256>>>(priors, targets);
    k_force<<<1, 64>>>();

    int totalWarps = BB * PP;
    int blocks = (totalWarps + 7) / 8;   // 8 warps (256 threads) per block
    k_main<<<blocks, 256>>>(loc, conf, obj, priors, targets);

    dim3 g2(2, BB);
    k_topk<<<g2, 256>>>();

    k_final<<<1, 1>>>(out);
}

// round 2
// speedup vs baseline: 1.0728x; 1.0728x over previous
#include <cuda_runtime.h>
#include <math.h>

#define BB 64
#define PP 16320
#define CC 81
#define OO 50

// ---------------- scratch (device globals; no allocation allowed) ----------------
__device__ float d_bto[BB * PP];   // best_truth_overlap
__device__ int   d_bti[BB * PP];   // best_truth_idx
__device__ int   d_bp [BB * OO];   // best prior per truth
__device__ float d_ce [BB * PP];   // shared neg CE (== conf CE == obj CE on negatives)
__device__ int   d_plist[BB * PP]; // compacted positive row indices
__device__ int   d_pcount;
__device__ int   d_npos[BB];
__device__ float d_acc[3];         // loss_l, loss_c, loss_obj accumulators

// ---------------- per-prior match (+ fused init) ----------------
__global__ void k_match_p(const float* __restrict__ priors,
                          const float* __restrict__ targets) {
    if (blockIdx.x == 0 && blockIdx.y == 0) {
        int t = threadIdx.x;
        if (t < 3) d_acc[t] = 0.f;
        if (t == 3) d_pcount = 0;
        if (t >= 32 && t < 32 + BB) d_npos[t - 32] = 0;
    }
    int b = blockIdx.y;
    __shared__ float s_t[OO * 5];
    if (threadIdx.x < OO * 5) s_t[threadIdx.x] = targets[b * OO * 5 + threadIdx.x];
    __syncthreads();
    int p = blockIdx.x * blockDim.x + threadIdx.x;
    if (p >= PP) return;

    float4 pr = ((const float4*)priors)[p];
    float px1 = pr.x - pr.z * 0.5f, py1 = pr.y - pr.w * 0.5f;
    float px2 = pr.x + pr.z * 0.5f, py2 = pr.y + pr.w * 0.5f;
    float pa = (px2 - px1) * (py2 - py1);

    float best = -1.0f; int bi = 0;
    #pragma unroll 5
    for (int o = 0; o < OO; o++) {
        float tx1 = s_t[o * 5 + 0], ty1 = s_t[o * 5 + 1];
        float tx2 = s_t[o * 5 + 2], ty2 = s_t[o * 5 + 3];
        float iw = fmaxf(fminf(tx2, px2) - fmaxf(tx1, px1), 0.f);
        float ih = fmaxf(fminf(ty2, py2) - fmaxf(ty1, py1), 0.f);
        float inter = iw * ih;
        float ta = (tx2 - tx1) * (ty2 - ty1);
        float ov = inter / (ta + pa - inter);
        if (ov > best) { best = ov; bi = o; }   // strict > == first-max (jnp.argmax)
    }
    d_bto[b * PP + p] = best;
    d_bti[b * PP + p] = bi;
}

// ---------------- per-truth match: argmax over priors (one block per (b,o)) --------
__global__ void k_match_o(const float* __restrict__ priors,
                          const float* __restrict__ targets) {
    int b = blockIdx.x / OO, o = blockIdx.x % OO;
    const float* t = targets + (b * OO + o) * 5;
    float tx1 = t[0], ty1 = t[1], tx2 = t[2], ty2 = t[3];
    float ta = (tx2 - tx1) * (ty2 - ty1);

    unsigned long long best = 0ull;
    for (int p = threadIdx.x; p < PP; p += blockDim.x) {
        float4 pr = ((const float4*)priors)[p];
        float px1 = pr.x - pr.z * 0.5f, py1 = pr.y - pr.w * 0.5f;
        float px2 = pr.x + pr.z * 0.5f, py2 = pr.y + pr.w * 0.5f;
        float pa = (px2 - px1) * (py2 - py1);
        float iw = fmaxf(fminf(tx2, px2) - fmaxf(tx1, px1), 0.f);
        float ih = fmaxf(fminf(ty2, py2) - fmaxf(ty1, py1), 0.f);
        float inter = iw * ih;
        float ov = inter / (ta + pa - inter);
        // IoU >= 0 so float bits are order-preserving; ~p breaks ties toward smaller p
        unsigned long long pk = ((unsigned long long)__float_as_uint(ov) << 32)
                              | (unsigned)(0xFFFFFFFFu - (unsigned)p);
        if (pk > best) best = pk;
    }
    __shared__ unsigned long long s[256];
    s[threadIdx.x] = best;
    __syncthreads();
    for (int st = 128; st; st >>= 1) {
        if (threadIdx.x < st) {
            unsigned long long oth = s[threadIdx.x + st];
            if (oth > s[threadIdx.x]) s[threadIdx.x] = oth;
        }
        __syncthreads();
    }
    if (threadIdx.x == 0)
        d_bp[b * OO + o] = (int)(0xFFFFFFFFu - (unsigned)(s[0] & 0xFFFFFFFFu));
}

// ---------------- force best-prior matches (parallel last-writer-wins) ----------------
__global__ void k_force() {
    int b = blockIdx.x;
    int o = threadIdx.x;
    __shared__ int sp[OO];
    if (o < OO) sp[o] = d_bp[b * OO + o];
    __syncthreads();
    if (o >= OO) return;
    int p = sp[o];
    // reference .at[idx].set: later truth index wins on duplicate priors
    for (int o2 = o + 1; o2 < OO; o2++)
        if (sp[o2] == p) return;
    d_bto[b * PP + p] = 2.0f;
    d_bti[b * PP + p] = o;
}

// ---------------- negative pass: softplus CE for every row, compact positives ------
// ce_c(neg) == ce_o(neg) == lse(obj) - obj0 == softplus(obj1 - obj0)
__global__ void __launch_bounds__(256) k_neg(const float* __restrict__ obj) {
    int i = blockIdx.x * blockDim.x + threadIdx.x;
    if (i >= BB * PP) return;
    float2 o = ((const float2*)obj)[i];
    float ddd = o.y - o.x;
    float sp_pos = fmaxf(ddd, 0.f) + __logf(1.f + __expf(-fabsf(ddd))); // lseo - o0
    bool pos = d_bto[i] >= 0.5f;
    d_ce[i] = pos ? 0.f : sp_pos;
    if (pos) {
        int b = i / PP;
        atomicAdd(&d_npos[b], 1);
        // ce_o(pos) = lseo - o1 = softplus(o0 - o1)
        float sp_neg = fmaxf(-ddd, 0.f) + __logf(1.f + __expf(-fabsf(ddd)));
        atomicAdd(&d_acc[2], sp_neg);
        int slot = atomicAdd(&d_pcount, 1);
        d_plist[slot] = i;
    }
}

// ---------------- positive pass: warp per positive row --------------------------------
__global__ void __launch_bounds__(256) k_pos(const float* __restrict__ loc,
                                             const float* __restrict__ conf,
                                             const float* __restrict__ obj,
                                             const float* __restrict__ priors,
                                             const float* __restrict__ targets) {
    int nwarps = (gridDim.x * blockDim.x) >> 5;
    int w = (blockIdx.x * blockDim.x + threadIdx.x) >> 5;
    int lane = threadIdx.x & 31;
    int n = d_pcount;
    for (; w < n; w += nwarps) {
        int gw = d_plist[w];
        const float* crow = conf + (size_t)gw * CC;
        float a0 = crow[lane];
        float a1 = crow[lane + 32];
        float a2 = (lane < 17) ? crow[lane + 64] : -1e30f;

        float m = fmaxf(fmaxf(a0, a1), a2);
        #pragma unroll
        for (int s = 16; s; s >>= 1) m = fmaxf(m, __shfl_xor_sync(0xFFFFFFFFu, m, s));
        float sum = __expf(a0 - m) + __expf(a1 - m) + ((lane < 17) ? __expf(a2 - m) : 0.f);
        #pragma unroll
        for (int s = 16; s; s >>= 1) sum += __shfl_xor_sync(0xFFFFFFFFu, sum, s);

        if (lane == 0) {
            float L = m + __logf(sum);               // lse(conf row)
            int b = gw / PP;
            int p = gw - b * PP;
            int ti = d_bti[gw];
            const float* t = targets + (b * OO + ti) * 5;
            int cls = (int)t[4];                     // conf target - 1

            float2 ob = ((const float2*)obj)[gw];
            float mo = fmaxf(ob.x, ob.y);
            float lseo = mo + __logf(__expf(ob.x - mo) + __expf(ob.y - mo));

            // CE of combined (C+1)-way logit at class cls+1:
            // lse(combined) = L + lseo; logit = ob.y + crow[cls]
            float cec = L + lseo - ob.y - crow[cls];
            atomicAdd(&d_acc[1], cec);

            // smooth-L1 localization loss
            float4 pr = ((const float4*)priors)[p];
            float x1 = t[0], y1 = t[1], x2 = t[2], y2 = t[3];
            float lt0 = ((x1 + x2) * 0.5f - pr.x) / (0.1f * pr.z);
            float lt1 = ((y1 + y2) * 0.5f - pr.y) / (0.1f * pr.w);
            float lt2 = __logf((x2 - x1) / pr.z) * 5.0f;   // /0.2
            float lt3 = __logf((y2 - y1) / pr.w) * 5.0f;
            float4 ld = ((const float4*)loc)[gw];
            float sacc = 0.f, d;
            d = ld.x - lt0; sacc += (fabsf(d) < 1.f) ? 0.5f * d * d : fabsf(d) - 0.5f;
            d = ld.y - lt1; sacc += (fabsf(d) < 1.f) ? 0.5f * d * d : fabsf(d) - 0.5f;
            d = ld.z - lt2; sacc += (fabsf(d) < 1.f) ? 0.5f * d * d : fabsf(d) - 0.5f;
            d = ld.w - lt3; sacc += (fabsf(d) < 1.f) ? 0.5f * d * d : fabsf(d) - 0.5f;
            atomicAdd(&d_acc[0], sacc);
        }
    }
}

// ---------------- top-k sum (exact, 4x8-bit radix select) — feeds BOTH losses --------
__global__ void __launch_bounds__(256) k_topk() {
    int b = blockIdx.x;
    const float* arr = d_ce + (size_t)b * PP;
    int k = 3 * d_npos[b];
    if (k > PP - 1) k = PP - 1;
    if (k <= 0) return;

    __shared__ unsigned hist[256];
    __shared__ unsigned s_prefix;
    __shared__ int s_krem;
    unsigned prefix = 0;
    int krem = k;

    for (int pass = 0; pass < 4; pass++) {
        hist[threadIdx.x] = 0;
        __syncthreads();
        int shift = 24 - 8 * pass;
        for (int p = threadIdx.x; p < PP; p += blockDim.x) {
            unsigned u = __float_as_uint(arr[p]);   // values >= 0 -> uint order == float order
            if (pass == 0 || (u >> (shift + 8)) == prefix)
                atomicAdd(&hist[(u >> shift) & 0xFF], 1u);
        }
        __syncthreads();
        if (threadIdx.x == 0) {
            int cum = 0, bin = 255;
            for (; bin > 0; bin--) {
                int c = (int)hist[bin];
                if (cum + c >= krem) break;
                cum += c;
            }
            s_prefix = (prefix << 8) | (unsigned)bin;
            s_krem = krem - cum;
        }
        __syncthreads();
        prefix = s_prefix;
        krem = s_krem;
        __syncthreads();
    }
    unsigned vbits = prefix;
    float v = __uint_as_float(vbits);

    float sum = 0.f; int cnt = 0;
    for (int p = threadIdx.x; p < PP; p += blockDim.x) {
        float x = arr[p];
        if (__float_as_uint(x) > vbits) { sum += x; cnt++; }
    }
    __shared__ float ss[256];
    __shared__ int sc[256];
    ss[threadIdx.x] = sum; sc[threadIdx.x] = cnt;
    __syncthreads();
    for (int st = 128; st; st >>= 1) {
        if (threadIdx.x < st) {
            ss[threadIdx.x] += ss[threadIdx.x + st];
            sc[threadIdx.x] += sc[threadIdx.x + st];
        }
        __syncthreads();
    }
    if (threadIdx.x == 0) {
        float S = ss[0] + (float)(k - sc[0]) * v;   // exact top-k sum
        atomicAdd(&d_acc[1], S);                    // conf-loss negatives
        atomicAdd(&d_acc[2], S);                    // obj-loss negatives (same array!)
    }
}

// ---------------- finalize ----------------
__global__ void k_final(float* __restrict__ out) {
    int n = 0;
    for (int b = 0; b < BB; b++) n += d_npos[b];
    float N = (float)n;
    out[0] = d_acc[0] / N;
    out[1] = d_acc[1] / N;
    out[2] = d_acc[2] / N;
}

// ---------------- launch ----------------
extern "C" void kernel_launch(void* const* d_in, const int* in_sizes, int n_in,
                              void* d_out, int out_size) {
    const float* loc     = (const float*)d_in[0];
    const float* conf    = (const float*)d_in[1];
    const float* obj     = (const float*)d_in[2];
    const float* priors  = (const float*)d_in[3];
    const float* targets = (const float*)d_in[4];
    float* out = (float*)d_out;

    dim3 g1((PP + 255) / 256, BB);
    k_match_p<<<g1, 256>>>(priors, targets);
    k_match_o<<<BB * OO, 256>>>(priors, targets);
    k_force<<<BB, 64>>>();

    k_neg<<<(BB * PP + 255) / 256, 256>>>(obj);
    k_pos<<<256, 256>>>(loc, conf, obj, priors, targets);

    k_topk<<<BB, 256>>>();
    k_final<<<1, 1>>>(out);
}

// round 3
// speedup vs baseline: 2.8395x; 2.6470x over previous
#include <cuda_runtime.h>
#include <math.h>

#define BB 64
#define PP 16320
#define CC 81
#define OO 50

// ---------------- scratch ----------------
__device__ int   d_pos_f[BB * PP];  // positive flag
__device__ int   d_bti[BB * PP];    // best_truth_idx
__device__ int   d_bp [BB * OO];    // best prior per truth
__device__ float d_ce [BB * PP];    // shared neg CE (conf CE == obj CE on negatives)
__device__ int   d_plist[BB * PP];  // compacted positive row indices
__device__ int   d_pcount;
__device__ int   d_npos[BB];
__device__ float d_accB[BB * 4];    // per-batch accumulators: [b][0]=loc,[1]=conf,[2]=obj

// ---------------- per-prior match (+ fused init); division-free ----------------
__global__ void __launch_bounds__(256) k_match_p(const float* __restrict__ priors,
                                                 const float* __restrict__ targets) {
    int tid = threadIdx.x;
    if (blockIdx.x == 0 && blockIdx.y == 0) {
        d_accB[tid] = 0.f;              // 256 = BB*4
        if (tid < BB) d_npos[tid] = 0;
        if (tid == 255) d_pcount = 0;
    }
    int b = blockIdx.y;
    __shared__ float4 s_c[OO];
    __shared__ float  s_a[OO];
    if (tid < OO) {
        const float* t = targets + (b * OO + tid) * 5;
        float4 c = make_float4(t[0], t[1], t[2], t[3]);
        s_c[tid] = c;
        s_a[tid] = (c.z - c.x) * (c.w - c.y);
    }
    __syncthreads();
    int p = blockIdx.x * 256 + tid;
    if (p >= PP) return;

    float4 pr = ((const float4*)priors)[p];
    float px1 = pr.x - pr.z * 0.5f, py1 = pr.y - pr.w * 0.5f;
    float px2 = pr.x + pr.z * 0.5f, py2 = pr.y + pr.w * 0.5f;
    float pa = (px2 - px1) * (py2 - py1);

    float bnum = 0.f, bden = 1.f; int bio = 0;
    #pragma unroll 5
    for (int o = 0; o < OO; o++) {
        float4 c = s_c[o];
        float iw = fmaxf(fminf(c.z, px2) - fmaxf(c.x, px1), 0.f);
        float ih = fmaxf(fminf(c.w, py2) - fmaxf(c.y, py1), 0.f);
        float inter = iw * ih;
        float den = pa + s_a[o] - inter;
        bool better = inter * bden > bnum * den;   // strict > keeps first max
        bnum = better ? inter : bnum;
        bden = better ? den   : bden;
        bio  = better ? o     : bio;
    }
    int i = b * PP + p;
    d_pos_f[i] = (bnum + bnum >= bden) ? 1 : 0;    // IoU >= 0.5
    d_bti[i] = bio;
}

// ---------------- per-truth argmax over priors: warp per (b,o), smem prior tiles ----
#define TILE 2048
__global__ void __launch_bounds__(320) k_match_o(const float* __restrict__ priors,
                                                 const float* __restrict__ targets) {
    __shared__ float4 s_pr[TILE];
    int tid = threadIdx.x;
    int lane = tid & 31, wid = tid >> 5;
    int b = blockIdx.y;
    int o = blockIdx.x * 10 + wid;

    const float* t = targets + (b * OO + o) * 5;
    float tx1 = t[0], ty1 = t[1], tx2 = t[2], ty2 = t[3];
    float ta = (tx2 - tx1) * (ty2 - ty1);

    float bnum = 0.f, bden = 1.f; int bidx = lane;

    for (int base = 0; base < PP; base += TILE) {
        int tn = min(TILE, PP - base);
        __syncthreads();
        for (int i = tid; i < tn; i += 320)
            s_pr[i] = ((const float4*)priors)[base + i];
        __syncthreads();
        #pragma unroll 4
        for (int j = lane; j < tn; j += 32) {
            float4 pr = s_pr[j];
            float px1 = pr.x - pr.z * 0.5f, py1 = pr.y - pr.w * 0.5f;
            float px2 = pr.x + pr.z * 0.5f, py2 = pr.y + pr.w * 0.5f;
            float pa = (px2 - px1) * (py2 - py1);
            float iw = fmaxf(fminf(tx2, px2) - fmaxf(tx1, px1), 0.f);
            float ih = fmaxf(fminf(ty2, py2) - fmaxf(ty1, py1), 0.f);
            float inter = iw * ih;
            float den = pa + ta - inter;
            bool better = inter * bden > bnum * den;
            bnum = better ? inter : bnum;
            bden = better ? den   : bden;
            bidx = better ? (base + j) : bidx;
        }
    }
    // one division per thread, then exact u64-key warp max (tie -> smaller p)
    float ratio = bnum / bden;
    unsigned long long key = ((unsigned long long)__float_as_uint(ratio) << 32)
                           | (unsigned)(0xFFFFFFFFu - (unsigned)bidx);
    #pragma unroll
    for (int s = 16; s; s >>= 1) {
        unsigned long long oth = __shfl_xor_sync(0xFFFFFFFFu, key, s);
        if (oth > key) key = oth;
    }
    if (lane == 0)
        d_bp[b * OO + o] = (int)(0xFFFFFFFFu - (unsigned)(key & 0xFFFFFFFFu));
}

// ---------------- force best-prior matches (parallel last-writer-wins) ----------------
__global__ void k_force() {
    int b = blockIdx.x;
    int o = threadIdx.x;
    __shared__ int sp[OO];
    if (o < OO) sp[o] = d_bp[b * OO + o];
    __syncthreads();
    if (o >= OO) return;
    int p = sp[o];
    for (int o2 = o + 1; o2 < OO; o2++)      // later truth wins on duplicate priors
        if (sp[o2] == p) return;
    d_pos_f[b * PP + p] = 1;
    d_bti[b * PP + p] = o;
}

// ---------------- negative pass: warp-aggregated atomics ----------------
__global__ void __launch_bounds__(256) k_neg(const float* __restrict__ obj) {
    int i = blockIdx.x * 256 + threadIdx.x;
    int lane = threadIdx.x & 31;
    float2 o = ((const float2*)obj)[i];
    float ddd = o.y - o.x;
    float lt = __logf(1.f + __expf(-fabsf(ddd)));
    bool pos = d_pos_f[i] != 0;
    d_ce[i] = pos ? 0.f : (fmaxf(ddd, 0.f) + lt);      // softplus(o1-o0) = lseo - o0

    unsigned mask = __ballot_sync(0xFFFFFFFFu, pos);
    if (mask == 0) return;
    int b = i / PP;                                     // PP % 32 == 0: warp-uniform
    float spn = pos ? (fmaxf(-ddd, 0.f) + lt) : 0.f;    // ce_o(pos) = lseo - o1
    #pragma unroll
    for (int s = 16; s; s >>= 1) spn += __shfl_xor_sync(0xFFFFFFFFu, spn, s);
    int cnt = __popc(mask);
    int leader = __ffs(mask) - 1;
    int slot = 0;
    if (lane == leader) {
        slot = atomicAdd(&d_pcount, cnt);
        atomicAdd(&d_npos[b], cnt);
        atomicAdd(&d_accB[b * 4 + 2], spn);
    }
    slot = __shfl_sync(0xFFFFFFFFu, slot, leader);
    if (pos)
        d_plist[slot + __popc(mask & ((1u << lane) - 1))] = i;
}

// ---------------- positive pass: warp per positive row ----------------
__global__ void __launch_bounds__(256) k_pos(const float* __restrict__ loc,
                                             const float* __restrict__ conf,
                                             const float* __restrict__ obj,
                                             const float* __restrict__ priors,
                                             const float* __restrict__ targets) {
    int nwarps = (gridDim.x * blockDim.x) >> 5;
    int w = (blockIdx.x * blockDim.x + threadIdx.x) >> 5;
    int lane = threadIdx.x & 31;
    int n = d_pcount;
    for (; w < n; w += nwarps) {
        int gw = d_plist[w];
        const float* crow = conf + (size_t)gw * CC;
        float a0 = crow[lane];
        float a1 = crow[lane + 32];
        float a2 = (lane < 17) ? crow[lane + 64] : -1e30f;

        float m = fmaxf(fmaxf(a0, a1), a2);
        #pragma unroll
        for (int s = 16; s; s >>= 1) m = fmaxf(m, __shfl_xor_sync(0xFFFFFFFFu, m, s));
        float sum = __expf(a0 - m) + __expf(a1 - m) + ((lane < 17) ? __expf(a2 - m) : 0.f);
        #pragma unroll
        for (int s = 16; s; s >>= 1) sum += __shfl_xor_sync(0xFFFFFFFFu, sum, s);

        if (lane == 0) {
            float L = m + __logf(sum);                  // lse(conf row)
            int b = gw / PP;
            int p = gw - b * PP;
            int ti = d_bti[gw];
            const float* t = targets + (b * OO + ti) * 5;
            int cls = (int)t[4];

            float2 ob = ((const float2*)obj)[gw];
            float mo = fmaxf(ob.x, ob.y);
            float lseo = mo + __logf(__expf(ob.x - mo) + __expf(ob.y - mo));
            // CE of (C+1)-way combined logit at class cls+1: lse = L + lseo
            atomicAdd(&d_accB[b * 4 + 1], L + lseo - ob.y - crow[cls]);

            float4 pr = ((const float4*)priors)[p];
            float x1 = t[0], y1 = t[1], x2 = t[2], y2 = t[3];
            float lt0 = ((x1 + x2) * 0.5f - pr.x) / (0.1f * pr.z);
            float lt1 = ((y1 + y2) * 0.5f - pr.y) / (0.1f * pr.w);
            float lt2 = __logf((x2 - x1) / pr.z) * 5.0f;
            float lt3 = __logf((y2 - y1) / pr.w) * 5.0f;
            float4 ld = ((const float4*)loc)[gw];
            float sacc = 0.f, d;
            d = ld.x - lt0; sacc += (fabsf(d) < 1.f) ? 0.5f * d * d : fabsf(d) - 0.5f;
            d = ld.y - lt1; sacc += (fabsf(d) < 1.f) ? 0.5f * d * d : fabsf(d) - 0.5f;
            d = ld.z - lt2; sacc += (fabsf(d) < 1.f) ? 0.5f * d * d : fabsf(d) - 0.5f;
            d = ld.w - lt3; sacc += (fabsf(d) < 1.f) ? 0.5f * d * d : fabsf(d) - 0.5f;
            atomicAdd(&d_accB[b * 4 + 0], sacc);
        }
    }
}

// ---------------- top-k sum (exact radix select) — feeds BOTH losses ----------------
__global__ void __launch_bounds__(512) k_topk() {
    int b = blockIdx.x;
    const float* arr = d_ce + (size_t)b * PP;
    int k = 3 * d_npos[b];
    if (k > PP - 1) k = PP - 1;
    if (k <= 0) return;

    __shared__ unsigned hist[256];
    __shared__ unsigned s_prefix;
    __shared__ int s_krem;
    unsigned prefix = 0;
    int krem = k;

    for (int pass = 0; pass < 4; pass++) {
        if (threadIdx.x < 256) hist[threadIdx.x] = 0;
        __syncthreads();
        int shift = 24 - 8 * pass;
        for (int p = threadIdx.x; p < PP; p += 512) {
            unsigned u = __float_as_uint(arr[p]);
            if (pass == 0 || (u >> (shift + 8)) == prefix)
                atomicAdd(&hist[(u >> shift) & 0xFF], 1u);
        }
        __syncthreads();
        if (threadIdx.x == 0) {
            int cum = 0, bin = 255;
            for (; bin > 0; bin--) {
                int c = (int)hist[bin];
                if (cum + c >= krem) break;
                cum += c;
            }
            s_prefix = (prefix << 8) | (unsigned)bin;
            s_krem = krem - cum;
        }
        __syncthreads();
        prefix = s_prefix;
        krem = s_krem;
        __syncthreads();
    }
    unsigned vbits = prefix;
    float v = __uint_as_float(vbits);

    float sum = 0.f; int cnt = 0;
    for (int p = threadIdx.x; p < PP; p += 512) {
        float x = arr[p];
        if (__float_as_uint(x) > vbits) { sum += x; cnt++; }
    }
    __shared__ float ss[512];
    __shared__ int sc[512];
    ss[threadIdx.x] = sum; sc[threadIdx.x] = cnt;
    __syncthreads();
    for (int st = 256; st; st >>= 1) {
        if (threadIdx.x < st) {
            ss[threadIdx.x] += ss[threadIdx.x + st];
            sc[threadIdx.x] += sc[threadIdx.x + st];
        }
        __syncthreads();
    }
    if (threadIdx.x == 0) {
        float S = ss[0] + (float)(k - sc[0]) * v;   // exact top-k sum
        atomicAdd(&d_accB[b * 4 + 1], S);           // conf negatives
        atomicAdd(&d_accB[b * 4 + 2], S);           // obj negatives (same array)
    }
}

// ---------------- finalize ----------------
__global__ void k_final(float* __restrict__ out) {
    float l0 = 0.f, l1 = 0.f, l2 = 0.f; int n = 0;
    for (int b = 0; b < BB; b++) {
        l0 += d_accB[b * 4 + 0];
        l1 += d_accB[b * 4 + 1];
        l2 += d_accB[b * 4 + 2];
        n  += d_npos[b];
    }
    float N = (float)n;
    out[0] = l0 / N;
    out[1] = l1 / N;
    out[2] = l2 / N;
}

// ---------------- launch ----------------
extern "C" void kernel_launch(void* const* d_in, const int* in_sizes, int n_in,
                              void* d_out, int out_size) {
    const float* loc     = (const float*)d_in[0];
    const float* conf    = (const float*)d_in[1];
    const float* obj     = (const float*)d_in[2];
    const float* priors  = (const float*)d_in[3];
    const float* targets = (const float*)d_in[4];
    float* out = (float*)d_out;

    dim3 g1((PP + 255) / 256, BB);
    k_match_p<<<g1, 256>>>(priors, targets);
    dim3 g2(5, BB);                       // 5 truth-groups x 10 warps = 50 truths
    k_match_o<<<g2, 320>>>(priors, targets);
    k_force<<<BB, 64>>>();

    k_neg<<<(BB * PP) / 256, 256>>>(obj);
    k_pos<<<256, 256>>>(loc, conf, obj, priors, targets);

    k_topk<<<BB, 512>>>();
    k_final<<<1, 1>>>(out);
}